// round 4
// baseline (speedup 1.0000x reference)
#include <cuda_runtime.h>
#include <math.h>

// YearOperatorRouter: per-sample routed 3x3 edge magnitude.
// All three operators share the form kx = [[-p,0,p],[-q,0,q],[-p,0,p]], ky = kx^T.
// out = sqrt(gx^2 + gy^2 + eps) * s, zero ("SAME") padding.

#define W 256
#define H 256

__device__ __forceinline__ void load_row6(const float* __restrict__ row, int x0, float r[6]) {
    // 6-wide window [x0-1 .. x0+4]; x0 is a multiple of 4 so the middle 4 are one float4.
    float4 m = __ldg(reinterpret_cast<const float4*>(row + x0));
    r[0] = (x0 > 0) ? __ldg(row + x0 - 1) : 0.0f;
    r[1] = m.x; r[2] = m.y; r[3] = m.z; r[4] = m.w;
    r[5] = (x0 + 4 < W) ? __ldg(row + x0 + 4) : 0.0f;
}

__device__ __forceinline__ void zero_row6(float r[6]) {
#pragma unroll
    for (int j = 0; j < 6; j++) r[j] = 0.0f;
}

__global__ __launch_bounds__(256, 8)
void year_router_kernel(const float* __restrict__ x,
                        const float* __restrict__ alpha,
                        const float* __restrict__ scale,
                        const int*   __restrict__ year,
                        float* __restrict__ out,
                        int C)
{
    const int x0 = threadIdx.x * 4;                                   // 0..252 (blockDim.x = 64)
    const int y0 = (blockIdx.y * blockDim.y + threadIdx.y) * 4;       // 0..252 (gridDim.y = 16, blockDim.y = 4)
    const int bc = blockIdx.z;                                        // 0..B*C-1
    const int b  = bc / C;

    // ---- per-sample operator parameters (branch is uniform per z-block) ----
    const int yr = __ldg(year + b);
    float p, q, eps, s;
    if (yr == 2019) {            // sobel
        p = 1.0f; q = 2.0f; eps = 1e-8f; s = 1.0f;
    } else if (yr == 2020) {     // scharr
        p = 3.0f; q = 10.0f; eps = 1e-8f; s = 1.0f;
    } else {                     // learnable: sigmoid mix, normalized by max|k| = q-term
        float a  = 1.0f / (1.0f + expf(-__ldg(alpha)));
        float pm = 3.0f  - 2.0f * a;
        float qm = 10.0f - 8.0f * a;   // qm > pm > 0 for a in (0,1) -> max|k| = qm
        p = pm / qm; q = 1.0f;
        eps = 1e-6f;
        s = 1.0f / (1.0f + expf(-__ldg(scale)));
    }

    const float* __restrict__ base  = x   + (size_t)bc * H * W;
    float*       __restrict__ obase = out + (size_t)bc * H * W;

    // ---- rolling 3-row register window over a 4-row strip ----
    float rows[3][6];
    if (y0 > 0) load_row6(base + (size_t)(y0 - 1) * W, x0, rows[0]);
    else        zero_row6(rows[0]);
    load_row6(base + (size_t)y0 * W, x0, rows[1]);

#pragma unroll
    for (int i = 0; i < 4; i++) {
        const int yn = y0 + i + 1;
        float* rn = rows[(i + 2) % 3];
        if (yn < H) load_row6(base + (size_t)yn * W, x0, rn);
        else        zero_row6(rn);

        const float* r0 = rows[(i + 0) % 3];   // y-1
        const float* r1 = rows[(i + 1) % 3];   // y
        const float* r2 = rn;                  // y+1

        float o[4];
#pragma unroll
        for (int j = 0; j < 4; j++) {
            // gx = p*(a02-a00) + q*(a12-a10) + p*(a22-a20)
            float gx = p * (r0[j + 2] - r0[j])
                     + q * (r1[j + 2] - r1[j])
                     + p * (r2[j + 2] - r2[j]);
            // gy = p*(a20-a00) + q*(a21-a01) + p*(a22-a02)
            float gy = p * (r2[j]     - r0[j])
                     + q * (r2[j + 1] - r0[j + 1])
                     + p * (r2[j + 2] - r0[j + 2]);
            o[j] = sqrtf(gx * gx + gy * gy + eps) * s;
        }
        *reinterpret_cast<float4*>(obase + (size_t)(y0 + i) * W + x0) =
            make_float4(o[0], o[1], o[2], o[3]);
    }
}

extern "C" void kernel_launch(void* const* d_in, const int* in_sizes, int n_in,
                              void* d_out, int out_size)
{
    const float* x     = (const float*)d_in[0];   // [B, C, 256, 256] f32
    const float* alpha = (const float*)d_in[1];   // scalar f32
    const float* scale = (const float*)d_in[2];   // [1] f32
    const int*   year  = (const int*)d_in[3];     // [B] int32
    float* out = (float*)d_out;

    const int B  = in_sizes[3];
    const int BC = in_sizes[0] / (H * W);
    const int C  = BC / B;

    dim3 block(64, 4, 1);          // 64*4 px in x via float4, 4 row-threads
    dim3 grid(1, H / (4 * 4), BC); // 16 strips of 16 rows... (4 rows/thread * 4 thread-rows)

    year_router_kernel<<<grid, block>>>(x, alpha, scale, year, out, C);
}